// round 14
// baseline (speedup 1.0000x reference)
#include <cuda_runtime.h>
#include <math.h>

#define NS     64
#define HID    20
#define HDIM   1280
#define BATCH  16384
#define MROWS  8
#define T      384             // 12 warps = 4 levels x 3 warps, reg cap 168
#define NJW    48              // j-stride per level (3 warps x 16 j)
#define LVL    806400          // floats per level (2016*400)

typedef unsigned long long ull;

// fc2..fc5 scatter weights, ull-chunk layout (k-split across lane pair):
//   slab si (nt=(63-si)*20 targets): ull at [k2*nt + j] = (W[j][2k2], W[j][2k2+1]), k2=0..9
__device__ ull   g_Ws2[2 * LVL];        // 4 levels x LVL floats = 12.9 MB
__device__ float g_W1s[2016 * 20];      // fc1 scalar, j-major
__device__ float g_W6s[2016 * 20];      // fc6 chunk-major: (k, t) float4
__device__ float g_Wd [64 * 2020];      // diag per si: [lv*400 + ci*20 + c], fc6 at 2000

__device__ __forceinline__ int slab_off1(int si) { return 63 * si - (si * (si - 1)) / 2; }

__global__ void prep_scatter(const float* __restrict__ W1, const float* __restrict__ W2,
                             const float* __restrict__ W3, const float* __restrict__ W4,
                             const float* __restrict__ W5, const float* __restrict__ W6)
{
    const int si = blockIdx.x, what = blockIdx.y;
    const int nso1 = 63 - si;
    const int nt = nso1 * 20;
    if (what < 4) {
        const float* W = (what == 0) ? W2 : (what == 1) ? W3 : (what == 2) ? W4 : W5;
        float* dst = (float*)g_Ws2 + (size_t)what * LVL + (size_t)slab_off1(si) * 400;
        const int cnt = nso1 * 400;
        for (int t = threadIdx.x; t < cnt; t += blockDim.x) {
            int m = t & 1, q = t >> 1;
            int j = q % nt, k2 = q / nt;
            int so = si + 1 + j / 20, c = j % 20, ci = 2 * k2 + m;
            dst[t] = W[(size_t)(c * NS + so) * HDIM + ci * NS + si];
        }
    } else if (what == 4) {
        float* d1 = g_W1s + (size_t)slab_off1(si) * 20;
        for (int t = threadIdx.x; t < nt; t += blockDim.x) {
            int so = si + 1 + t / 20, c = t % 20;
            d1[t] = W1[(size_t)(c * NS + so) * NS + si];
        }
        float* dd = g_Wd + (size_t)si * 2020;
        for (int t = threadIdx.x; t < 2020; t += blockDim.x) {
            if (t < 1600) {
                int lv = t / 400, rem = t - lv * 400;
                int ci = rem / 20, c = rem - ci * 20;
                const float* W = (lv == 0) ? W2 : (lv == 1) ? W3 : (lv == 2) ? W4 : W5;
                dd[t] = W[(size_t)(c * NS + si) * HDIM + ci * NS + si];
            } else if (t < 2000) {
                dd[t] = 0.0f;
            } else {
                dd[t] = W6[(size_t)si * HDIM + (t - 2000) * NS + si];
            }
        }
    } else {
        float* d6 = g_W6s + (size_t)slab_off1(si) * 20;
        const int cnt = nso1 * 20;
        for (int t = threadIdx.x; t < cnt; t += blockDim.x) {
            int m = t & 3, q = t >> 2;
            int tt = q % nso1, k = q / nso1;
            int so = si + 1 + tt, ci = 4 * k + m;
            d6[t] = W6[(size_t)so * HDIM + ci * NS + si];
        }
    }
}

__device__ __forceinline__ ull ffma2(ull a, ull b, ull c)
{
    ull d;
    asm("fma.rn.f32x2 %0, %1, %2, %3;" : "=l"(d) : "l"(a), "l"(b), "l"(c));
    return d;
}
__device__ __forceinline__ ull pack2(float lo, float hi)
{
    ull v;
    asm("mov.b64 %0, {%1, %2};" : "=l"(v) : "f"(lo), "f"(hi));
    return v;
}
__device__ __forceinline__ float hsum2(ull v)
{
    float lo, hi;
    asm("mov.b64 {%0, %1}, %2;" : "=f"(lo), "=f"(hi) : "l"(v));
    return lo + hi;
}
__device__ __forceinline__ float sigmoidf(float x) { return 1.0f / (1.0f + expf(-x)); }

#define BAR_DIAG() asm volatile("bar.sync 1, 160;" ::: "memory")

// pipeline stage: 5 LDG.64 weight chunks (k-split by grp) + float4 dst (4 own rows)
#define WLOAD(W, D, jj) do {                                                    \
    int jc_ = ((jj) < nt) ? (jj) : 0;                                           \
    (W)[0] = *(const ull*)(wb + ((size_t)(kofs + 0) * nt + jc_) * 2);           \
    (W)[1] = *(const ull*)(wb + ((size_t)(kofs + 1) * nt + jc_) * 2);           \
    (W)[2] = *(const ull*)(wb + ((size_t)(kofs + 2) * nt + jc_) * 2);           \
    (W)[3] = *(const ull*)(wb + ((size_t)(kofs + 3) * nt + jc_) * 2);           \
    (W)[4] = *(const ull*)(wb + ((size_t)(kofs + 4) * nt + jc_) * 2);           \
    (D)    = *(const float4*)(prl + (size_t)jc_ * 8 + rb);                      \
} while (0)

// compute: 8-row partial dots over this grp's 10 ci, bfly exchange, store own 4 rows
#define WCOMP(W, D, jj) do {                                                    \
    ull a0 = 0ull, a1 = 0ull, a2 = 0ull, a3 = 0ull;                             \
    ull a4 = 0ull, a5 = 0ull, a6 = 0ull, a7 = 0ull;                             \
    _Pragma("unroll")                                                           \
    for (int q = 0; q < 5; ++q) {                                               \
        a0 = ffma2((W)[q], hr[0][q], a0);                                       \
        a1 = ffma2((W)[q], hr[1][q], a1);                                       \
        a2 = ffma2((W)[q], hr[2][q], a2);                                       \
        a3 = ffma2((W)[q], hr[3][q], a3);                                       \
        a4 = ffma2((W)[q], hr[4][q], a4);                                       \
        a5 = ffma2((W)[q], hr[5][q], a5);                                       \
        a6 = ffma2((W)[q], hr[6][q], a6);                                       \
        a7 = ffma2((W)[q], hr[7][q], a7);                                       \
    }                                                                           \
    float p0 = hsum2(a0), p1 = hsum2(a1), p2 = hsum2(a2), p3 = hsum2(a3);       \
    float p4 = hsum2(a4), p5 = hsum2(a5), p6 = hsum2(a6), p7 = hsum2(a7);       \
    float s0 = grp ? p0 : p4;   /* send partner's rows */                       \
    float s1 = grp ? p1 : p5;                                                   \
    float s2 = grp ? p2 : p6;                                                   \
    float s3 = grp ? p3 : p7;                                                   \
    float g0 = __shfl_xor_sync(0xffffffffu, s0, 1);                             \
    float g1 = __shfl_xor_sync(0xffffffffu, s1, 1);                             \
    float g2 = __shfl_xor_sync(0xffffffffu, s2, 1);                             \
    float g3 = __shfl_xor_sync(0xffffffffu, s3, 1);                             \
    float m0 = grp ? p4 : p0;   /* own rows partial */                          \
    float m1 = grp ? p5 : p1;                                                   \
    float m2 = grp ? p6 : p2;                                                   \
    float m3 = grp ? p7 : p3;                                                   \
    if ((jj) < nt) {                                                            \
        float4 o;                                                               \
        o.x = m0 + g0 + (D).x;                                                  \
        o.y = m1 + g1 + (D).y;                                                  \
        o.z = m2 + g2 + (D).z;                                                  \
        o.w = m3 + g3 + (D).w;                                                  \
        *(float4*)(prl + (size_t)(jj) * 8 + rb) = o;                            \
    }                                                                           \
} while (0)

__global__ void __launch_bounds__(T, 1)
net_kernel(const float* __restrict__ u, float* __restrict__ out)
{
    extern __shared__ float sm[];
    float* pre  = sm;                        // [5][1280][8]  col-major rows
    float* pre6 = pre + 5 * HDIM * MROWS;    // [64][8]
    float* hbt  = pre6 + NS * MROWS;         // [5][8][20]
    float* usm  = hbt + 5 * 160;             // [8][64]
    float* wd   = usm + 512;                 // [2020]
    float* sv   = wd + 2020;                 // [8]

    const int tid  = threadIdx.x;
    const int lane = tid & 31;
    const int wid  = tid >> 5;
    const int lv   = wid & 3;                     // this warp's scatter level
    const int wgrp = wid >> 2;                    // 0..2
    const int jw0  = wgrp * 16 + (lane >> 1);     // base target col lane: 0..47
    const int grp  = lane & 1;                    // k-half & row-group
    const int rb   = grp * 4;                     // rows rb..rb+3 owned
    const int kofs = 5 * grp;                     // ull-chunk offset
    // fc6 lanes (2-row mapping)
    const int pair = tid & 3, jl = tid >> 2;
    const int r0 = 2 * pair;

    for (int k = tid; k < 5 * HDIM * MROWS; k += T) pre[k] = 0.0f;
    for (int k = tid; k < NS * MROWS; k += T) pre6[k] = 0.0f;
    for (int k = tid; k < 512; k += T) {
        int ii = k >> 3, rr = k & 7;
        usm[rr * NS + ii] = u[(size_t)ii * BATCH + (size_t)blockIdx.x * MROWS + rr];
    }
    for (int k = tid; k < 2020; k += T) wd[k] = g_Wd[k];
    __syncthreads();

    for (int i = 0; i < NS; ++i) {
        // ===== diagonal chain: 160 threads (warps 0-4) =====
        if (tid < 160) {
            const int dr = tid / 20, dc = tid - (tid / 20) * 20;
            hbt[dr * 20 + dc] = sigmoidf(pre[(i * HID + dc) * 8 + dr]);
            BAR_DIAG();
            #pragma unroll 1
            for (int dlv = 0; dlv < 4; ++dlv) {
                float acc = pre[(size_t)(dlv + 1) * HDIM * MROWS + (i * HID + dc) * 8 + dr];
                float acc2 = 0.0f;
                const float* w   = wd + dlv * 400 + dc;
                const float* hh_ = hbt + dlv * 160 + dr * 20;
                #pragma unroll
                for (int ci = 0; ci < 10; ++ci) {
                    acc  = fmaf(w[(2 * ci)     * 20], hh_[2 * ci],     acc);
                    acc2 = fmaf(w[(2 * ci + 1) * 20], hh_[2 * ci + 1], acc2);
                }
                hbt[(dlv + 1) * 160 + dr * 20 + dc] = sigmoidf(acc + acc2);
                BAR_DIAG();
            }
            if (tid < MROWS) {                           // fc6 diag + sample
                float acc = pre6[i * 8 + tid];
                const float* hh_ = hbt + 4 * 160 + tid * 20;
                #pragma unroll
                for (int ci = 0; ci < 20; ++ci) acc = fmaf(wd[2000 + ci], hh_[ci], acc);
                float x = sigmoidf(acc);
                out[((size_t)blockIdx.x * MROWS + tid) * NS + i] = x;
                sv[tid] = (x >= usm[tid * NS + i]) ? 1.0f : -1.0f;
            }
        }
        __syncthreads();

        // ===== scatter phase =====
        if (i < 63) {
            const int nso1 = 63 - i;
            const int nt = nso1 * HID;
            const int tbase = (i + 1) * HID;
            const size_t soff = (size_t)slab_off1(i);

            // fc2..fc5 — level-per-warp, k-split lane pairs (1x weight delivery),
            // float4 dst RMW, 2-deep ping-pong on weights+dst
            {
                const float* wb = (const float*)g_Ws2 + (size_t)lv * LVL + soff * 400;
                float* prl = pre + (size_t)(lv + 1) * HDIM * MROWS + (size_t)tbase * 8;
                ull hr[8][5];
                #pragma unroll
                for (int r = 0; r < 8; ++r) {
                    const ull* hp = (const ull*)(hbt + lv * 160 + r * 20 + grp * 10);
                    #pragma unroll
                    for (int q = 0; q < 5; ++q) hr[r][q] = hp[q];
                }
                int trips = (nt > wgrp * 16) ? (nt - wgrp * 16 + NJW - 1) / NJW : 0;
                if (trips > 0) {
                    ull wA[5], wB[5];
                    float4 dA, dB;
                    int jj = jw0;
                    WLOAD(wA, dA, jj);
                    for (;;) {
                        if (trips == 1) { WCOMP(wA, dA, jj); break; }
                        int j1 = jj + NJW;
                        WLOAD(wB, dB, j1);
                        WCOMP(wA, dA, jj);
                        if (--trips == 1) { WCOMP(wB, dB, j1); break; }
                        jj = j1 + NJW;
                        WLOAD(wA, dA, jj);
                        WCOMP(wB, dB, j1);
                        --trips;
                    }
                }
            }
            // fc6 (single round, lanes jl < nso1)
            if (jl < nso1) {
                const float* wb6 = g_W6s + soff * 20;
                const ull* hp0 = (const ull*)(hbt + 4 * 160 + r0 * 20);
                const ull* hp1 = (const ull*)(hbt + 4 * 160 + (r0 + 1) * 20);
                float* dpf = pre6 + (size_t)(i + 1 + jl) * 8 + r0;
                float dd0 = dpf[0], dd1 = dpf[1];
                ull a0 = 0ull, a1 = 0ull;
                #pragma unroll
                for (int k = 0; k < 5; ++k) {
                    ulonglong2 wv = *(const ulonglong2*)(wb6 + ((size_t)k * nso1 + jl) * 4);
                    a0 = ffma2(wv.x, hp0[2 * k], a0); a0 = ffma2(wv.y, hp0[2 * k + 1], a0);
                    a1 = ffma2(wv.x, hp1[2 * k], a1); a1 = ffma2(wv.y, hp1[2 * k + 1], a1);
                }
                dpf[0] = hsum2(a0) + dd0;
                dpf[1] = hsum2(a1) + dd1;
            }
            // fc1 rank-1 — packed ull pairs on contiguous [col][row8] dst
            {
                const float* wb1 = g_W1s + soff * 20;
                const ull* sv64 = (const ull*)sv;        // (s0,s1)(s2,s3)(s4,s5)(s6,s7)
                ull sva = sv64[0], svb = sv64[1], svc = sv64[2], svdd = sv64[3];
                for (int j = tid; j < nt; j += T) {
                    float w = wb1[j];
                    ull w2 = pack2(w, w);
                    ull* d = (ull*)(pre + ((size_t)(tbase + j)) * 8);
                    d[0] = ffma2(w2, sva, d[0]);
                    d[1] = ffma2(w2, svb, d[1]);
                    d[2] = ffma2(w2, svc, d[2]);
                    d[3] = ffma2(w2, svdd, d[3]);
                }
            }
            // prefetch next step's diag weights
            {
                const float* src = g_Wd + (size_t)(i + 1) * 2020;
                for (int k = tid; k < 2020; k += T) wd[k] = src[k];
            }
        }
        __syncthreads();
    }
}

extern "C" void kernel_launch(void* const* d_in, const int* in_sizes, int n_in,
                              void* d_out, int out_size)
{
    (void)in_sizes; (void)n_in; (void)out_size;
    const float* u  = (const float*)d_in[1];
    const float* W1 = (const float*)d_in[2];
    const float* W2 = (const float*)d_in[3];
    const float* W3 = (const float*)d_in[4];
    const float* W4 = (const float*)d_in[5];
    const float* W5 = (const float*)d_in[6];
    const float* W6 = (const float*)d_in[7];
    float* out = (float*)d_out;

    dim3 pg(64, 6);
    prep_scatter<<<pg, 256>>>(W1, W2, W3, W4, W5, W6);

    const int smem_bytes = (5 * HDIM * MROWS + NS * MROWS + 5 * 160
                            + 512 + 2020 + 8) * (int)sizeof(float);   // ~220 KB
    cudaFuncSetAttribute(net_kernel, cudaFuncAttributeMaxDynamicSharedMemorySize, smem_bytes);
    net_kernel<<<BATCH / MROWS, T, smem_bytes>>>(u, out);
}

// round 15
// speedup vs baseline: 1.0467x; 1.0467x over previous
#include <cuda_runtime.h>
#include <math.h>

#define NS     64
#define HID    20
#define HDIM   1280
#define BATCH  16384
#define MROWS  4
#define T      256             // 8 warps/CTA, 2 CTAs/SM
#define NJW    32              // j-stride per level (2 warp-groups x 16 j)
#define PSTR   1288            // 2*PSTR % 32 == 16 -> pair rows hit disjoint banks
#define LVL    806400          // 2016*400 floats per level

typedef unsigned long long ull;

// Chunk-major scatter weights (best measured layout):
//   slab si (nt=(63-si)*20 targets): float4 at [k*nt + j] = W[j][4k..4k+3]
__device__ float g_Ws4[4 * LVL];
__device__ float g_W1s[2016 * 20];      // fc1 scalar, j-major
__device__ float g_W6s[2016 * 20];      // fc6 chunk-major: (k, t) float4
__device__ float g_Wd [64 * 2020];      // diag per si: [lv*400 + ci*20 + c], fc6 at 2000

__device__ __forceinline__ int slab_off1(int si) { return 63 * si - (si * (si - 1)) / 2; }

__global__ void prep_scatter(const float* __restrict__ W1, const float* __restrict__ W2,
                             const float* __restrict__ W3, const float* __restrict__ W4,
                             const float* __restrict__ W5, const float* __restrict__ W6)
{
    const int si = blockIdx.x, what = blockIdx.y;
    const int nso1 = 63 - si;
    const int nt = nso1 * 20;
    if (what < 4) {
        const float* W = (what == 0) ? W2 : (what == 1) ? W3 : (what == 2) ? W4 : W5;
        float* dst = g_Ws4 + (size_t)what * LVL + (size_t)slab_off1(si) * 400;
        const int cnt = nso1 * 400;
        for (int t = threadIdx.x; t < cnt; t += blockDim.x) {
            int m = t & 3, q = t >> 2;
            int j = q % nt, k = q / nt;
            int so = si + 1 + j / 20, c = j % 20, ci = 4 * k + m;
            dst[t] = W[(size_t)(c * NS + so) * HDIM + ci * NS + si];
        }
    } else if (what == 4) {
        float* d1 = g_W1s + (size_t)slab_off1(si) * 20;
        for (int t = threadIdx.x; t < nt; t += blockDim.x) {
            int so = si + 1 + t / 20, c = t % 20;
            d1[t] = W1[(size_t)(c * NS + so) * NS + si];
        }
        float* dd = g_Wd + (size_t)si * 2020;
        for (int t = threadIdx.x; t < 2020; t += blockDim.x) {
            if (t < 1600) {
                int lv = t / 400, rem = t - lv * 400;
                int ci = rem / 20, c = rem - ci * 20;
                const float* W = (lv == 0) ? W2 : (lv == 1) ? W3 : (lv == 2) ? W4 : W5;
                dd[t] = W[(size_t)(c * NS + si) * HDIM + ci * NS + si];
            } else if (t < 2000) {
                dd[t] = 0.0f;
            } else {
                dd[t] = W6[(size_t)si * HDIM + (t - 2000) * NS + si];
            }
        }
    } else {
        float* d6 = g_W6s + (size_t)slab_off1(si) * 20;
        const int cnt = nso1 * 20;
        for (int t = threadIdx.x; t < cnt; t += blockDim.x) {
            int m = t & 3, q = t >> 2;
            int tt = q % nso1, k = q / nso1;
            int so = si + 1 + tt, ci = 4 * k + m;
            d6[t] = W6[(size_t)so * HDIM + ci * NS + si];
        }
    }
}

__device__ __forceinline__ ull ffma2(ull a, ull b, ull c)
{
    ull d;
    asm("fma.rn.f32x2 %0, %1, %2, %3;" : "=l"(d) : "l"(a), "l"(b), "l"(c));
    return d;
}
__device__ __forceinline__ ull pack2(float lo, float hi)
{
    ull v;
    asm("mov.b64 %0, {%1, %2};" : "=l"(v) : "f"(lo), "f"(hi));
    return v;
}
__device__ __forceinline__ float hsum2(ull v)
{
    float lo, hi;
    asm("mov.b64 {%0, %1}, %2;" : "=f"(lo), "=f"(hi) : "l"(v));
    return lo + hi;
}
__device__ __forceinline__ float sigmoidf(float x) { return 1.0f / (1.0f + expf(-x)); }

#define BAR_DIAG() asm volatile("bar.sync 1, 96;" ::: "memory")

// pipeline stage: 5 weight chunks + 2-row dst for target j
#define WLOAD2(W, D, j) do {                                                    \
    (W)[0] = *(const ulonglong2*)(wb + ((size_t)0 * nt + (j)) * 4);             \
    (W)[1] = *(const ulonglong2*)(wb + ((size_t)1 * nt + (j)) * 4);             \
    (W)[2] = *(const ulonglong2*)(wb + ((size_t)2 * nt + (j)) * 4);             \
    (W)[3] = *(const ulonglong2*)(wb + ((size_t)3 * nt + (j)) * 4);             \
    (W)[4] = *(const ulonglong2*)(wb + ((size_t)4 * nt + (j)) * 4);             \
    (D)[0] = prl[(rb + 0) * PSTR + (j)];                                        \
    (D)[1] = prl[(rb + 1) * PSTR + (j)];                                        \
} while (0)

// compute stage: 40-MAC (2 rows x 20 ci), fold prefetched dst, store
#define WCOMP2(W, D, j) do {                                                    \
    ull a0 = 0ull, a1 = 0ull;                                                   \
    _Pragma("unroll")                                                           \
    for (int q = 0; q < 5; ++q) {                                               \
        a0 = ffma2((W)[q].x, hh[0][2*q],   a0);                                 \
        a1 = ffma2((W)[q].x, hh[1][2*q],   a1);                                 \
        a0 = ffma2((W)[q].y, hh[0][2*q+1], a0);                                 \
        a1 = ffma2((W)[q].y, hh[1][2*q+1], a1);                                 \
    }                                                                           \
    prl[(rb + 0) * PSTR + (j)] = hsum2(a0) + (D)[0];                            \
    prl[(rb + 1) * PSTR + (j)] = hsum2(a1) + (D)[1];                            \
} while (0)

__global__ void __launch_bounds__(T, 2)
net_kernel(const float* __restrict__ u, float* __restrict__ out)
{
    extern __shared__ float sm[];
    float* pre  = sm;                        // [5][4][PSTR]
    float* pre6 = pre + 5 * MROWS * PSTR;    // [4][68]
    float* hbt  = pre6 + MROWS * 68;         // [5][4][20]
    float* usm  = hbt + 5 * 80;              // [4][64]
    float* wd   = usm + 256;                 // [2020]
    float* sv   = wd + 2020;                 // [4]+pad

    const int tid  = threadIdx.x;
    const int lane = tid & 31;
    const int wid  = tid >> 5;
    const int lv   = wid & 3;                     // this warp's scatter level
    const int wgrp = wid >> 2;                    // 0..1
    const int jw0  = wgrp * 16 + (lane >> 1);     // j-lane within level: 0..31
    const int grp  = lane & 1;                    // row group (rows grp*2..grp*2+1)
    const int rb   = grp * 2;
    // fc6 lanes
    const int pair = tid & 1, jl = tid >> 1;      // jl 0..127
    const int r0 = 2 * pair;

    for (int k = tid; k < 5 * MROWS * PSTR; k += T) pre[k] = 0.0f;
    for (int k = tid; k < MROWS * 68; k += T) pre6[k] = 0.0f;
    {
        int ii = tid >> 2, rr = tid & 3;          // 256 threads cover [4][64]
        usm[rr * NS + ii] = u[(size_t)ii * BATCH + (size_t)blockIdx.x * MROWS + rr];
    }
    for (int k = tid; k < 2020; k += T) wd[k] = g_Wd[k];
    __syncthreads();

    for (int i = 0; i < NS; ++i) {
        // ===== diagonal chain: 96 threads (80 active), named barrier =====
        if (tid < 96) {
            const int dr = tid / 20, dc = tid - (tid / 20) * 20;   // valid for tid<80
            if (tid < 80)
                hbt[dr * 20 + dc] = sigmoidf(pre[dr * PSTR + i * HID + dc]);
            BAR_DIAG();
            #pragma unroll 1
            for (int dlv = 0; dlv < 4; ++dlv) {
                if (tid < 80) {
                    float acc = pre[((dlv + 1) * MROWS + dr) * PSTR + i * HID + dc];
                    float acc2 = 0.0f;
                    const float* w   = wd + dlv * 400 + dc;
                    const float* hh_ = hbt + dlv * 80 + dr * 20;
                    #pragma unroll
                    for (int ci = 0; ci < 10; ++ci) {
                        acc  = fmaf(w[(2 * ci)     * 20], hh_[2 * ci],     acc);
                        acc2 = fmaf(w[(2 * ci + 1) * 20], hh_[2 * ci + 1], acc2);
                    }
                    hbt[(dlv + 1) * 80 + dr * 20 + dc] = sigmoidf(acc + acc2);
                }
                BAR_DIAG();
            }
            if (tid < MROWS) {                           // fc6 diag + sample
                float acc = pre6[tid * 68 + i];
                const float* hh_ = hbt + 4 * 80 + tid * 20;
                #pragma unroll
                for (int ci = 0; ci < 20; ++ci) acc = fmaf(wd[2000 + ci], hh_[ci], acc);
                float x = sigmoidf(acc);
                out[((size_t)blockIdx.x * MROWS + tid) * NS + i] = x;
                sv[tid] = (x >= usm[tid * NS + i]) ? 1.0f : -1.0f;
            }
        }
        __syncthreads();

        // ===== scatter phase =====
        if (i < 63) {
            const int nso1 = 63 - i;
            const int nt = nso1 * HID;
            const int tbase = (i + 1) * HID;
            const size_t soff = (size_t)slab_off1(i);

            // fc2..fc5 — level-per-warp (2 warps/level), 2 rows/lane,
            // 2-deep ping-pong on weights+dst
            {
                const float* wb = g_Ws4 + (size_t)lv * LVL + soff * 400;
                float* prl = pre + (size_t)(lv + 1) * MROWS * PSTR + tbase;
                ull hh[2][10];
                #pragma unroll
                for (int t = 0; t < 2; ++t) {
                    const ull* hp = (const ull*)(hbt + lv * 80 + (rb + t) * 20);
                    #pragma unroll
                    for (int q = 0; q < 10; ++q) hh[t][q] = hp[q];
                }
                int j0 = jw0;
                if (j0 < nt) {
                    ulonglong2 wA[5], wB[5];
                    float dA[2], dB[2];
                    WLOAD2(wA, dA, j0);
                    for (;;) {
                        int j1 = j0 + NJW;
                        if (j1 >= nt) { WCOMP2(wA, dA, j0); break; }
                        WLOAD2(wB, dB, j1);
                        WCOMP2(wA, dA, j0);
                        j0 = j1 + NJW;
                        if (j0 >= nt) { WCOMP2(wB, dB, j1); break; }
                        WLOAD2(wA, dA, j0);
                        WCOMP2(wB, dB, j1);
                    }
                }
            }
            // fc6 (single round, lanes jl < nso1; 2 rows per lane)
            if (jl < nso1) {
                const float* wb6 = g_W6s + soff * 20;
                const ull* hp0 = (const ull*)(hbt + 4 * 80 + r0 * 20);
                const ull* hp1 = (const ull*)(hbt + 4 * 80 + (r0 + 1) * 20);
                float* dp0 = pre6 + (r0)     * 68 + (i + 1 + jl);
                float* dp1 = pre6 + (r0 + 1) * 68 + (i + 1 + jl);
                float dd0 = *dp0, dd1 = *dp1;
                ull a0 = 0ull, a1 = 0ull;
                #pragma unroll
                for (int k = 0; k < 5; ++k) {
                    ulonglong2 wv = *(const ulonglong2*)(wb6 + ((size_t)k * nso1 + jl) * 4);
                    a0 = ffma2(wv.x, hp0[2 * k], a0); a0 = ffma2(wv.y, hp0[2 * k + 1], a0);
                    a1 = ffma2(wv.x, hp1[2 * k], a1); a1 = ffma2(wv.y, hp1[2 * k + 1], a1);
                }
                *dp0 = hsum2(a0) + dd0;
                *dp1 = hsum2(a1) + dd1;
            }
            // fc1 rank-1
            {
                const float* wb1 = g_W1s + soff * 20;
                float* p1 = pre + tbase;
                float s0 = sv[0], s1 = sv[1], s2 = sv[2], s3 = sv[3];
                for (int j = tid; j < nt; j += T) {
                    float w = wb1[j];
                    p1[0 * PSTR + j] += w * s0;  p1[1 * PSTR + j] += w * s1;
                    p1[2 * PSTR + j] += w * s2;  p1[3 * PSTR + j] += w * s3;
                }
            }
            // prefetch next step's diag weights
            {
                const float* src = g_Wd + (size_t)(i + 1) * 2020;
                for (int k = tid; k < 2020; k += T) wd[k] = src[k];
            }
        }
        __syncthreads();
    }
}

extern "C" void kernel_launch(void* const* d_in, const int* in_sizes, int n_in,
                              void* d_out, int out_size)
{
    (void)in_sizes; (void)n_in; (void)out_size;
    const float* u  = (const float*)d_in[1];
    const float* W1 = (const float*)d_in[2];
    const float* W2 = (const float*)d_in[3];
    const float* W3 = (const float*)d_in[4];
    const float* W4 = (const float*)d_in[5];
    const float* W5 = (const float*)d_in[6];
    const float* W6 = (const float*)d_in[7];
    float* out = (float*)d_out;

    dim3 pg(64, 6);
    prep_scatter<<<pg, 256>>>(W1, W2, W3, W4, W5, W6);

    const int smem_bytes = (5 * MROWS * PSTR + MROWS * 68 + 5 * 80
                            + 256 + 2020 + 8) * (int)sizeof(float);   // ~114.7 KB -> 2 CTAs/SM
    cudaFuncSetAttribute(net_kernel, cudaFuncAttributeMaxDynamicSharedMemorySize, smem_bytes);
    net_kernel<<<BATCH / MROWS, T, smem_bytes>>>(u, out);
}

// round 16
// speedup vs baseline: 1.1301x; 1.0797x over previous
#include <cuda_runtime.h>
#include <math.h>

#define NS     64
#define HID    20
#define HDIM   1280
#define BATCH  16384
#define MROWS  4
#define T      256             // 8 warps/CTA, 2 CTAs/SM
#define LSTR   (HDIM * MROWS)  // 5120 floats per pre level ([col][row4])
#define LVL    806400          // 2016*400 floats per level

typedef unsigned long long ull;

// Chunk-major scatter weights (best measured layout):
//   slab si (nt=(63-si)*20 targets): float4 at [k*nt + j] = W[j][4k..4k+3]
__device__ float g_Ws4[4 * LVL];
__device__ float g_W1s[2016 * 20];      // fc1 scalar, j-major
__device__ float g_W6s[2016 * 20];      // fc6 chunk-major: (k, t) float4
__device__ float g_Wd [64 * 1620];      // diag per si: fc2-5 [lv*400+ci*20+c], fc6 at 1600

__device__ __forceinline__ int slab_off1(int si) { return 63 * si - (si * (si - 1)) / 2; }

__global__ void prep_scatter(const float* __restrict__ W1, const float* __restrict__ W2,
                             const float* __restrict__ W3, const float* __restrict__ W4,
                             const float* __restrict__ W5, const float* __restrict__ W6)
{
    const int si = blockIdx.x, what = blockIdx.y;
    const int nso1 = 63 - si;
    const int nt = nso1 * 20;
    if (what < 4) {
        const float* W = (what == 0) ? W2 : (what == 1) ? W3 : (what == 2) ? W4 : W5;
        float* dst = g_Ws4 + (size_t)what * LVL + (size_t)slab_off1(si) * 400;
        const int cnt = nso1 * 400;
        for (int t = threadIdx.x; t < cnt; t += blockDim.x) {
            int m = t & 3, q = t >> 2;
            int j = q % nt, k = q / nt;
            int so = si + 1 + j / 20, c = j % 20, ci = 4 * k + m;
            dst[t] = W[(size_t)(c * NS + so) * HDIM + ci * NS + si];
        }
    } else if (what == 4) {
        float* d1 = g_W1s + (size_t)slab_off1(si) * 20;
        for (int t = threadIdx.x; t < nt; t += blockDim.x) {
            int so = si + 1 + t / 20, c = t % 20;
            d1[t] = W1[(size_t)(c * NS + so) * NS + si];
        }
        float* dd = g_Wd + (size_t)si * 1620;
        for (int t = threadIdx.x; t < 1620; t += blockDim.x) {
            if (t < 1600) {
                int lv = t / 400, rem = t - lv * 400;
                int ci = rem / 20, c = rem - ci * 20;
                const float* W = (lv == 0) ? W2 : (lv == 1) ? W3 : (lv == 2) ? W4 : W5;
                dd[t] = W[(size_t)(c * NS + si) * HDIM + ci * NS + si];
            } else {
                dd[t] = W6[(size_t)si * HDIM + (t - 1600) * NS + si];
            }
        }
    } else {
        float* d6 = g_W6s + (size_t)slab_off1(si) * 20;
        const int cnt = nso1 * 20;
        for (int t = threadIdx.x; t < cnt; t += blockDim.x) {
            int m = t & 3, q = t >> 2;
            int tt = q % nso1, k = q / nso1;
            int so = si + 1 + tt, ci = 4 * k + m;
            d6[t] = W6[(size_t)so * HDIM + ci * NS + si];
        }
    }
}

__device__ __forceinline__ ull ffma2(ull a, ull b, ull c)
{
    ull d;
    asm("fma.rn.f32x2 %0, %1, %2, %3;" : "=l"(d) : "l"(a), "l"(b), "l"(c));
    return d;
}
__device__ __forceinline__ ull pack2(float lo, float hi)
{
    ull v;
    asm("mov.b64 %0, {%1, %2};" : "=l"(v) : "f"(lo), "f"(hi));
    return v;
}
__device__ __forceinline__ float hsum2(ull v)
{
    float lo, hi;
    asm("mov.b64 {%0, %1}, %2;" : "=f"(lo), "=f"(hi) : "l"(v));
    return lo + hi;
}
__device__ __forceinline__ float sigmoidf(float x) { return 1.0f / (1.0f + expf(-x)); }

#define BAR_DIAG() asm volatile("bar.sync 1, 96;" ::: "memory")

__global__ void __launch_bounds__(T, 2)
net_kernel(const float* __restrict__ u, float* __restrict__ out)
{
    extern __shared__ float sm[];
    float* pre  = sm;                        // [5][1280][4]  col-major rows
    float* pre6 = pre + 5 * LSTR;            // [64][4]
    float* hbt  = pre6 + NS * MROWS;         // [5][4][20]
    float* usm  = hbt + 5 * 80;              // [4][64]  (rr*64+ii)
    float* wd   = usm + 256;                 // [1620]
    float* sv   = wd + 1620;                 // [8] (4 used, 8B aligned)

    const int tid  = threadIdx.x;
    const int lane = tid & 31;
    const int wid  = tid >> 5;
    const int lv   = wid & 3;                // this warp's scatter level
    const int wgrp = wid >> 2;               // 0..1
    const int jw0  = wgrp * 32 + lane;       // distinct j per lane: 0..63

    for (int k = tid; k < 5 * LSTR; k += T) pre[k] = 0.0f;
    for (int k = tid; k < NS * MROWS; k += T) pre6[k] = 0.0f;
    {
        int ii = tid >> 2, rr = tid & 3;     // 256 threads cover [4][64]
        usm[rr * NS + ii] = u[(size_t)ii * BATCH + (size_t)blockIdx.x * MROWS + rr];
    }
    for (int k = tid; k < 1620; k += T) wd[k] = g_Wd[k];
    __syncthreads();

    for (int i = 0; i < NS; ++i) {
        // ===== diagonal chain: 96 threads (80 active), named barrier =====
        if (tid < 96) {
            const int dr = tid / 20, dc = tid - (tid / 20) * 20;
            if (tid < 80)
                hbt[dr * 20 + dc] = sigmoidf(pre[(i * HID + dc) * 4 + dr]);
            BAR_DIAG();
            #pragma unroll 1
            for (int dlv = 0; dlv < 4; ++dlv) {
                if (tid < 80) {
                    float acc = pre[(dlv + 1) * LSTR + (i * HID + dc) * 4 + dr];
                    float acc2 = 0.0f;
                    const float* w   = wd + dlv * 400 + dc;
                    const float* hh_ = hbt + dlv * 80 + dr * 20;
                    #pragma unroll
                    for (int ci = 0; ci < 10; ++ci) {
                        acc  = fmaf(w[(2 * ci)     * 20], hh_[2 * ci],     acc);
                        acc2 = fmaf(w[(2 * ci + 1) * 20], hh_[2 * ci + 1], acc2);
                    }
                    hbt[(dlv + 1) * 80 + dr * 20 + dc] = sigmoidf(acc + acc2);
                }
                BAR_DIAG();
            }
            if (tid < MROWS) {                           // fc6 diag + sample
                float acc = pre6[i * 4 + tid];
                const float* hh_ = hbt + 4 * 80 + tid * 20;
                #pragma unroll
                for (int ci = 0; ci < 20; ++ci) acc = fmaf(wd[1600 + ci], hh_[ci], acc);
                float x = sigmoidf(acc);
                out[((size_t)blockIdx.x * MROWS + tid) * NS + i] = x;
                sv[tid] = (x >= usm[tid * NS + i]) ? 1.0f : -1.0f;
            }
        }
        __syncthreads();

        // ===== scatter phase =====
        if (i < 63) {
            const int nso1 = 63 - i;
            const int nt = nso1 * HID;
            const int tbase = (i + 1) * HID;
            const size_t soff = (size_t)slab_off1(i);

            // fc2..fc5 — level-per-warp (2 warps/level), 4 rows/lane,
            // 32 distinct j per warp: every weight byte delivered once
            {
                const float* wb = g_Ws4 + (size_t)lv * LVL + soff * 400;
                float* prl = pre + (lv + 1) * LSTR + tbase * 4;
                ull hh[4][10];
                #pragma unroll
                for (int r = 0; r < 4; ++r) {
                    const ull* hp = (const ull*)(hbt + lv * 80 + r * 20);
                    #pragma unroll
                    for (int q = 0; q < 10; ++q) hh[r][q] = hp[q];
                }
                #pragma unroll 1
                for (int j = jw0; j < nt; j += 64) {
                    float4 d = *(const float4*)(prl + (size_t)j * 4);
                    ulonglong2 w0 = *(const ulonglong2*)(wb + ((size_t)0 * nt + j) * 4);
                    ulonglong2 w1 = *(const ulonglong2*)(wb + ((size_t)1 * nt + j) * 4);
                    ulonglong2 w2 = *(const ulonglong2*)(wb + ((size_t)2 * nt + j) * 4);
                    ulonglong2 w3 = *(const ulonglong2*)(wb + ((size_t)3 * nt + j) * 4);
                    ulonglong2 w4 = *(const ulonglong2*)(wb + ((size_t)4 * nt + j) * 4);
                    ull a0 = 0ull, a1 = 0ull, a2 = 0ull, a3 = 0ull;
                    a0 = ffma2(w0.x, hh[0][0], a0); a1 = ffma2(w0.x, hh[1][0], a1);
                    a2 = ffma2(w0.x, hh[2][0], a2); a3 = ffma2(w0.x, hh[3][0], a3);
                    a0 = ffma2(w0.y, hh[0][1], a0); a1 = ffma2(w0.y, hh[1][1], a1);
                    a2 = ffma2(w0.y, hh[2][1], a2); a3 = ffma2(w0.y, hh[3][1], a3);
                    a0 = ffma2(w1.x, hh[0][2], a0); a1 = ffma2(w1.x, hh[1][2], a1);
                    a2 = ffma2(w1.x, hh[2][2], a2); a3 = ffma2(w1.x, hh[3][2], a3);
                    a0 = ffma2(w1.y, hh[0][3], a0); a1 = ffma2(w1.y, hh[1][3], a1);
                    a2 = ffma2(w1.y, hh[2][3], a2); a3 = ffma2(w1.y, hh[3][3], a3);
                    a0 = ffma2(w2.x, hh[0][4], a0); a1 = ffma2(w2.x, hh[1][4], a1);
                    a2 = ffma2(w2.x, hh[2][4], a2); a3 = ffma2(w2.x, hh[3][4], a3);
                    a0 = ffma2(w2.y, hh[0][5], a0); a1 = ffma2(w2.y, hh[1][5], a1);
                    a2 = ffma2(w2.y, hh[2][5], a2); a3 = ffma2(w2.y, hh[3][5], a3);
                    a0 = ffma2(w3.x, hh[0][6], a0); a1 = ffma2(w3.x, hh[1][6], a1);
                    a2 = ffma2(w3.x, hh[2][6], a2); a3 = ffma2(w3.x, hh[3][6], a3);
                    a0 = ffma2(w3.y, hh[0][7], a0); a1 = ffma2(w3.y, hh[1][7], a1);
                    a2 = ffma2(w3.y, hh[2][7], a2); a3 = ffma2(w3.y, hh[3][7], a3);
                    a0 = ffma2(w4.x, hh[0][8], a0); a1 = ffma2(w4.x, hh[1][8], a1);
                    a2 = ffma2(w4.x, hh[2][8], a2); a3 = ffma2(w4.x, hh[3][8], a3);
                    a0 = ffma2(w4.y, hh[0][9], a0); a1 = ffma2(w4.y, hh[1][9], a1);
                    a2 = ffma2(w4.y, hh[2][9], a2); a3 = ffma2(w4.y, hh[3][9], a3);
                    float4 o;
                    o.x = hsum2(a0) + d.x;
                    o.y = hsum2(a1) + d.y;
                    o.z = hsum2(a2) + d.z;
                    o.w = hsum2(a3) + d.w;
                    *(float4*)(prl + (size_t)j * 4) = o;
                }
            }
            // fc6 (single round, lanes tid < nso1; 4 rows per lane)
            if (tid < nso1) {
                const float* wb6 = g_W6s + soff * 20;
                const ull* h6 = (const ull*)(hbt + 4 * 80);     // rows at h6 + r*10
                float4 d = *(const float4*)(pre6 + (size_t)(i + 1 + tid) * 4);
                ull a0 = 0ull, a1 = 0ull, a2 = 0ull, a3 = 0ull;
                #pragma unroll
                for (int k = 0; k < 5; ++k) {
                    ulonglong2 wv = *(const ulonglong2*)(wb6 + ((size_t)k * nso1 + tid) * 4);
                    a0 = ffma2(wv.x, h6[0 * 10 + 2 * k], a0); a0 = ffma2(wv.y, h6[0 * 10 + 2 * k + 1], a0);
                    a1 = ffma2(wv.x, h6[1 * 10 + 2 * k], a1); a1 = ffma2(wv.y, h6[1 * 10 + 2 * k + 1], a1);
                    a2 = ffma2(wv.x, h6[2 * 10 + 2 * k], a2); a2 = ffma2(wv.y, h6[2 * 10 + 2 * k + 1], a2);
                    a3 = ffma2(wv.x, h6[3 * 10 + 2 * k], a3); a3 = ffma2(wv.y, h6[3 * 10 + 2 * k + 1], a3);
                }
                float4 o;
                o.x = hsum2(a0) + d.x;
                o.y = hsum2(a1) + d.y;
                o.z = hsum2(a2) + d.z;
                o.w = hsum2(a3) + d.w;
                *(float4*)(pre6 + (size_t)(i + 1 + tid) * 4) = o;
            }
            // fc1 rank-1 — packed row-pairs on [col][row4] dst
            {
                const float* wb1 = g_W1s + soff * 20;
                const ull* sv64 = (const ull*)sv;        // (s0,s1)(s2,s3)
                ull s01 = sv64[0], s23 = sv64[1];
                for (int j = tid; j < nt; j += T) {
                    float w = wb1[j];
                    ull w2 = pack2(w, w);
                    ull* d = (ull*)(pre + (size_t)(tbase + j) * 4);
                    d[0] = ffma2(w2, s01, d[0]);
                    d[1] = ffma2(w2, s23, d[1]);
                }
            }
            // prefetch next step's diag weights
            {
                const float* src = g_Wd + (size_t)(i + 1) * 1620;
                for (int k = tid; k < 1620; k += T) wd[k] = src[k];
            }
        }
        __syncthreads();
    }
}

extern "C" void kernel_launch(void* const* d_in, const int* in_sizes, int n_in,
                              void* d_out, int out_size)
{
    (void)in_sizes; (void)n_in; (void)out_size;
    const float* u  = (const float*)d_in[1];
    const float* W1 = (const float*)d_in[2];
    const float* W2 = (const float*)d_in[3];
    const float* W3 = (const float*)d_in[4];
    const float* W4 = (const float*)d_in[5];
    const float* W5 = (const float*)d_in[6];
    const float* W6 = (const float*)d_in[7];
    float* out = (float*)d_out;

    dim3 pg(64, 6);
    prep_scatter<<<pg, 256>>>(W1, W2, W3, W4, W5, W6);

    const int smem_bytes = (5 * LSTR + NS * MROWS + 5 * 80
                            + 256 + 1620 + 8) * (int)sizeof(float);   // 112.6 KB -> 2 CTAs/SM
    cudaFuncSetAttribute(net_kernel, cudaFuncAttributeMaxDynamicSharedMemorySize, smem_bytes);
    net_kernel<<<BATCH / MROWS, T, smem_bytes>>>(u, out);
}